// round 6
// baseline (speedup 1.0000x reference)
#include <cuda_runtime.h>

#define N_PTS 160000
#define QTR 40000
#define C 64
#define SCALE_XY 2073600
#define PID_SPACE (2*SCALE_XY)            /* 4,147,200 pids */
#define WORDS (PID_SPACE/2)               /* 2,073,600 u32 words, 2 pids/word */
#define NBLK 296                          /* 2 blocks/SM on 148 SMs (<=152) */
#define NTHR 256
#define GSZ (NBLK*NTHR)                   /* 75776 threads */
#define WPT 28                            /* words per thread in scan chunk */
#define CHUNK_W (NTHR*WPT)                /* 7168 */
#define WORDS_PAD (NBLK*CHUNK_W)          /* 2,121,728 >= WORDS */

// ---------------- static scratch ----------------
__device__ unsigned int       g_zmask32[WORDS_PAD];
__device__ unsigned int       g_vbase[PID_SPACE];
__device__ int                g_pidlist[N_PTS];
__device__ int                g_head[N_PTS];
__device__ int                g_next[N_PTS];
__device__ unsigned char      g_zi[N_PTS];
__device__ unsigned long long g_bsums[NBLK];
__device__ double             g_s[8];
__device__ double             g_m[36];
__device__ float              g_W2[512];
__device__ float              g_shift[C];
__device__ int                g_P;
__device__ int                g_barc;
__device__ volatile unsigned  g_barg;

__device__ __forceinline__ unsigned long long pack_ov(unsigned w) {
    unsigned occ = (unsigned)((w & 0xffffu) != 0u) + (unsigned)((w >> 16) != 0u);
    return ((unsigned long long)occ << 32) | (unsigned)__popc(w);
}

// generation-count grid barrier; all NBLK blocks are co-resident by construction.
// trailing __threadfence() (gpu scope) emits CCTL.IVALL -> invalidates stale L1.
__device__ __forceinline__ void gridbar() {
    __syncthreads();
    if (threadIdx.x == 0) {
        unsigned gen = g_barg;
        __threadfence();
        if (atomicAdd(&g_barc, 1) == NBLK - 1) {
            atomicExch(&g_barc, 0);
            __threadfence();
            g_barg = gen + 1;
        } else {
            while (g_barg == gen) { }
        }
    }
    __syncthreads();
    __threadfence();
}

__global__ void __launch_bounds__(NTHR, 2)
k_fused(const float* __restrict__ pts, const float* __restrict__ sparse,
        const float* __restrict__ W, const float* __restrict__ gamma,
        const float* __restrict__ beta, const int* __restrict__ pmc,
        float* __restrict__ out)
{
    int t = threadIdx.x, bid = blockIdx.x;
    int gtid = bid * NTHR + t;
    int lane = t & 31, wid = t >> 5;

    __shared__ unsigned long long s_woff[8];
    __shared__ unsigned long long s_red[8];
    __shared__ unsigned long long s_agg, s_exc;
    __shared__ double sd[44];
    __shared__ float sW2[512];
    __shared__ float sSh[64];

    // ================= P0: zero scratch =================
    {
        uint4 z4 = make_uint4(0u, 0u, 0u, 0u);
        uint4* zm = (uint4*)g_zmask32;
        for (int j = gtid; j < WORDS_PAD / 4; j += GSZ) zm[j] = z4;
        int4 m1 = make_int4(-1, -1, -1, -1);
        int4* hd = (int4*)g_head;
        for (int j = gtid; j < N_PTS / 4; j += GSZ) hd[j] = m1;
        if (gtid < 8)       g_s[gtid] = 0.0;
        else if (gtid < 44) g_m[gtid - 8] = 0.0;
    }
    gridbar();

    // ================= P1: moments + zmask + z side-channel =================
    {
        float s[8], m[36];
        #pragma unroll
        for (int k = 0; k < 8; k++) s[k] = 0.f;
        #pragma unroll
        for (int k = 0; k < 36; k++) m[k] = 0.f;
        for (int i = gtid; i < N_PTS; i += GSZ) {
            const float* p = pts + (size_t)i * 9;
            float x[8];
            #pragma unroll
            for (int k = 0; k < 8; k++) x[k] = p[1 + k];
            #pragma unroll
            for (int k = 0; k < 8; k++) {
                s[k] += x[k];
                #pragma unroll
                for (int l = 0; l <= k; l++) m[k * (k + 1) / 2 + l] += x[k] * x[l];
            }
            int zi = (int)x[5];                 // z in [0,16), voxel z size 1
            g_zi[i] = (unsigned char)zi;
            int pid = pmc[i];
            atomicOr(&g_zmask32[pid >> 1], (1u << zi) << ((pid & 1) * 16));
        }
        #pragma unroll
        for (int o = 16; o > 0; o >>= 1) {
            #pragma unroll
            for (int k = 0; k < 8; k++)  s[k] += __shfl_down_sync(0xffffffffu, s[k], o);
            #pragma unroll
            for (int k = 0; k < 36; k++) m[k] += __shfl_down_sync(0xffffffffu, m[k], o);
        }
        if (t < 44) sd[t] = 0.0;
        __syncthreads();
        if (lane == 0) {
            for (int k = 0; k < 8;  k++) atomicAdd(&sd[k],     (double)s[k]);
            for (int k = 0; k < 36; k++) atomicAdd(&sd[8 + k], (double)m[k]);
        }
        __syncthreads();
        if (t < 8)                 atomicAdd(&g_s[t],     sd[t]);
        else if (t < 44)           atomicAdd(&g_m[t - 8], sd[t]);
    }
    gridbar();

    // ================= P2: chunk reduce + BN fold =================
    unsigned w[WPT];
    size_t cbase = (size_t)bid * CHUNK_W + (size_t)t * WPT;
    #pragma unroll
    for (int k = 0; k < WPT; k += 4) {
        uint4 a = *(const uint4*)&g_zmask32[cbase + k];
        w[k] = a.x; w[k + 1] = a.y; w[k + 2] = a.z; w[k + 3] = a.w;
    }
    unsigned long long run = 0ULL;
    #pragma unroll
    for (int k = 0; k < WPT; k++) run += pack_ov(w[k]);
    unsigned long long inc = run;
    #pragma unroll
    for (int o = 1; o < 32; o <<= 1) {
        unsigned long long v = __shfl_up_sync(0xffffffffu, inc, o);
        if (lane >= o) inc += v;
    }
    if (lane == 31) s_woff[wid] = inc;
    __syncthreads();
    if (t < 8) {
        unsigned long long x = s_woff[t];
        unsigned long long sc = x;
        #pragma unroll
        for (int o = 1; o < 8; o <<= 1) {
            unsigned long long v = __shfl_up_sync(0xffu, sc, o);
            if (t >= o) sc += v;
        }
        s_woff[t] = sc - x;
        if (t == 7) s_agg = sc;
    }
    __syncthreads();
    if (t == 0) g_bsums[bid] = s_agg;
    if (bid == 0 && t >= 64 && t < 128) {   // BN fold overlaps other blocks
        int c = t - 64;
        double wc[8];
        #pragma unroll
        for (int k = 0; k < 8; k++) wc[k] = (double)W[k * 64 + c];
        const double invn = 1.0 / (double)N_PTS;
        double mu = 0.0;
        #pragma unroll
        for (int k = 0; k < 8; k++) mu += g_s[k] * invn * wc[k];
        double e2 = 0.0;
        #pragma unroll
        for (int k = 0; k < 8; k++) {
            for (int l = 0; l < k; l++) e2 += 2.0 * g_m[k * (k + 1) / 2 + l] * invn * wc[k] * wc[l];
            e2 += g_m[k * (k + 1) / 2 + k] * invn * wc[k] * wc[k];
        }
        double var = e2 - mu * mu;
        double scale = (double)gamma[c] / sqrt(var + 1e-3);
        #pragma unroll
        for (int k = 0; k < 8; k++) g_W2[k * 64 + c] = (float)(wc[k] * scale);
        g_shift[c] = (float)((double)beta[c] - mu * scale);
    }
    gridbar();

    // ================= P3: prefix over block sums + downsweep =================
    {
        unsigned long long p = 0ULL;
        if (t < bid) p = g_bsums[t];
        if (t + 256 < bid) p += g_bsums[t + 256];
        #pragma unroll
        for (int o = 16; o > 0; o >>= 1) p += __shfl_down_sync(0xffffffffu, p, o);
        if (lane == 0) s_red[wid] = p;
        __syncthreads();
        if (t == 0) {
            unsigned long long e = 0ULL;
            #pragma unroll
            for (int k = 0; k < 8; k++) e += s_red[k];
            s_exc = e;
            if (bid == NBLK - 1) g_P = (int)((e + s_agg) >> 32);
        }
        __syncthreads();
        unsigned long long cur = s_exc + s_woff[wid] + (inc - run);
        #pragma unroll
        for (int k = 0; k < WPT; k++) {
            unsigned ww = w[k];
            if (ww) {
                int pid0 = (int)((cbase + k) * 2);
                unsigned lo = ww & 0xffffu, hi = ww >> 16;
                if (lo) {
                    g_vbase[pid0] = (unsigned)cur;
                    g_pidlist[cur >> 32] = pid0;
                    cur += (1ULL << 32) + (unsigned)__popc(lo);
                }
                if (hi) {
                    g_vbase[pid0 + 1] = (unsigned)cur;
                    g_pidlist[cur >> 32] = pid0 + 1;
                    cur += (1ULL << 32) + (unsigned)__popc(hi);
                }
            }
        }
    }
    gridbar();

    // ================= P4: link points into per-voxel lists + smem preload ====
    for (int j = t; j < 512; j += NTHR) sW2[j] = g_W2[j];
    if (t < 64) sSh[t] = g_shift[t];
    if (gtid < QTR) {
        int idx[4], pid[4], zi[4];
        #pragma unroll
        for (int k = 0; k < 4; k++) {
            idx[k] = gtid + k * QTR;
            pid[k] = __ldg(&pmc[idx[k]]);
            zi[k]  = (int)g_zi[idx[k]];
        }
        unsigned wv[4]; unsigned vb[4];
        #pragma unroll
        for (int k = 0; k < 4; k++) wv[k] = g_zmask32[pid[k] >> 1];
        #pragma unroll
        for (int k = 0; k < 4; k++) vb[k] = g_vbase[pid[k]];
        #pragma unroll
        for (int k = 0; k < 4; k++) {
            unsigned zm = (wv[k] >> ((pid[k] & 1) * 16)) & 0xffffu;
            int slot = (int)vb[k] + __popc(zm & ((1u << zi[k]) - 1u));
            g_next[idx[k]] = atomicExch(&g_head[slot], idx[k]);
        }
    }
    gridbar();

    // ================= P5: output =================
    {
        int g = t >> 4, l4 = t & 15;
        int P = g_P;
        for (int r = bid * 16 + g; r < N_PTS; r += NBLK * 16) {
            float4 sv = ((const float4*)sparse)[(size_t)r * 16 + l4];
            float4 res = sv;
            if (r < P) {
                int pid = g_pidlist[r];
                unsigned wz = g_zmask32[pid >> 1];
                unsigned zm = (wz >> ((pid & 1) * 16)) & 0xffffu;
                int nv = __popc(zm);
                if (nv >= 2) {
                    int base = (int)g_vbase[pid];
                    int c0 = l4 * 4;
                    float4 mx = make_float4(-3.4e38f, -3.4e38f, -3.4e38f, -3.4e38f);
                    for (int j = 0; j < nv; j++) {
                        int idx = g_head[base + j];
                        float a0 = 0.f, a1 = 0.f, a2 = 0.f, a3 = 0.f;
                        int cnt = 0;
                        while (idx >= 0) {
                            const float* p = pts + (size_t)idx * 9;
                            int nxt = g_next[idx];
                            float x[8];
                            #pragma unroll
                            for (int k = 0; k < 8; k++) x[k] = __ldg(&p[1 + k]);
                            float h0 = sSh[c0], h1 = sSh[c0 + 1], h2 = sSh[c0 + 2], h3 = sSh[c0 + 3];
                            #pragma unroll
                            for (int k = 0; k < 8; k++) {
                                h0 = fmaf(x[k], sW2[k * 64 + c0],     h0);
                                h1 = fmaf(x[k], sW2[k * 64 + c0 + 1], h1);
                                h2 = fmaf(x[k], sW2[k * 64 + c0 + 2], h2);
                                h3 = fmaf(x[k], sW2[k * 64 + c0 + 3], h3);
                            }
                            a0 += fmaxf(h0, 0.f); a1 += fmaxf(h1, 0.f);
                            a2 += fmaxf(h2, 0.f); a3 += fmaxf(h3, 0.f);
                            cnt++;
                            idx = nxt;
                        }
                        float ic = 1.0f / (float)cnt;
                        mx.x = fmaxf(mx.x, a0 * ic);
                        mx.y = fmaxf(mx.y, a1 * ic);
                        mx.z = fmaxf(mx.z, a2 * ic);
                        mx.w = fmaxf(mx.w, a3 * ic);
                    }
                    float4 cand = make_float4(sv.x + mx.x, sv.y + mx.y, sv.z + mx.z, sv.w + mx.w);
                    if (nv < 16) {
                        cand.x = fmaxf(cand.x, 0.f); cand.y = fmaxf(cand.y, 0.f);
                        cand.z = fmaxf(cand.z, 0.f); cand.w = fmaxf(cand.w, 0.f);
                    }
                    res = make_float4(sv.x + cand.x, sv.y + cand.y, sv.z + cand.z, sv.w + cand.w);
                }
            }
            ((float4*)out)[(size_t)r * 16 + l4] = res;
        }
    }
}

// ---------------- launch: ONE kernel ----------------
extern "C" void kernel_launch(void* const* d_in, const int* in_sizes, int n_in,
                              void* d_out, int out_size) {
    const float* pts    = (const float*)d_in[0];
    const float* sparse = (const float*)d_in[1];
    const float* W      = (const float*)d_in[2];
    const float* gamma  = (const float*)d_in[3];
    const float* beta   = (const float*)d_in[4];
    const int*   pmc    = (const int*)d_in[5];
    float* out = (float*)d_out;

    k_fused<<<NBLK, NTHR>>>(pts, sparse, W, gamma, beta, pmc, out);
}